// round 16
// baseline (speedup 1.0000x reference)
#include <cuda_runtime.h>
#include <cuda_bf16.h>
#include <cstdint>
#include <cstdio>

#define B_ 64
#define T_ 512
#define EMB_ 128
#define HID_ 256
#define MEL_ 80
#define LMAX_ 2048

typedef unsigned long long ull;

// ---------------- static device scratch ----------------
__device__ int   g_durTab[256];
__device__ int   g_tok[B_ * LMAX_];                 // vocab id per expanded pos, 256 = pad
__device__ float g_projE[2 * 257 * 1024];           // Wih@embed[v] + bih + bhh  (entry 256 = bias only)
__device__ float g_hout[2ull * B_ * LMAX_ * HID_];  // [dir][b][pos][256]
__device__ uint4 g_linwF[320 * 32];                 // linw as B-frags: [kt*10+nt][lane]{hi0,hi1,lo0,lo1}

// ---------------- generic helpers ----------------
__device__ __forceinline__ ull fma2(ull a, ull b, ull c) {
    ull d;
    asm("fma.rn.f32x2 %0, %1, %2, %3;" : "=l"(d) : "l"(a), "l"(b), "l"(c));
    return d;
}
__device__ __forceinline__ float pairsum(ull v) {
    float x, y;
    asm("mov.b64 {%0, %1}, %2;" : "=f"(x), "=f"(y) : "l"(v));
    return x + y;
}
__device__ __forceinline__ float sigf(float x)  { return __fdividef(1.f, 1.f + __expf(-x)); }
__device__ __forceinline__ float tanhf_(float x){ return 1.f - __fdividef(2.f, 1.f + __expf(2.f * x)); }

__device__ __forceinline__ void cluster_sync() {
    asm volatile("barrier.cluster.arrive.aligned;" ::: "memory");
    asm volatile("barrier.cluster.wait.aligned;" ::: "memory");
}
__device__ __forceinline__ void mbar_init(uint32_t a, uint32_t cnt) {
    asm volatile("mbarrier.init.shared.b64 [%0], %1;" :: "r"(a), "r"(cnt) : "memory");
}
__device__ __forceinline__ void mbar_arrive_expect(uint32_t a, uint32_t tx) {
    asm volatile("mbarrier.arrive.expect_tx.shared.b64 _, [%0], %1;" :: "r"(a), "r"(tx) : "memory");
}
__device__ __forceinline__ void mbar_wait(uint32_t a, uint32_t par) {
    asm volatile(
        "{\n\t"
        ".reg .pred P;\n\t"
        "W%=:\n\t"
        "mbarrier.try_wait.parity.acquire.cluster.shared::cta.b64 P, [%0], %1, 0x989680;\n\t"
        "@P bra D%=;\n\t"
        "bra W%=;\n\t"
        "D%=:\n\t"
        "}"
        :: "r"(a), "r"(par) : "memory");
}
__device__ __forceinline__ void s2s_bulk(uint32_t dst, uint32_t src, uint32_t bytes, uint32_t rmbar) {
    asm volatile("cp.async.bulk.shared::cluster.shared::cta.mbarrier::complete_tx::bytes [%0], [%1], %2, [%3];"
                 :: "r"(dst), "r"(src), "r"(bytes), "r"(rmbar) : "memory");
}

__device__ __forceinline__ unsigned short bfb(float x) {
    __nv_bfloat16 h = __float2bfloat16(x);
    return reinterpret_cast<unsigned short&>(h);
}
__device__ __forceinline__ float bff(unsigned short u) {
    __nv_bfloat16 h = reinterpret_cast<__nv_bfloat16&>(u);
    return __bfloat162float(h);
}
__device__ __forceinline__ void packhl(float x, float y, uint32_t& hi, uint32_t& lo) {
    unsigned short h0 = bfb(x), h1 = bfb(y);
    float r0 = x - bff(h0), r1 = y - bff(h1);
    hi = (uint32_t)h0 | ((uint32_t)h1 << 16);
    lo = (uint32_t)bfb(r0) | ((uint32_t)bfb(r1) << 16);
}

// HMMA m16n8k16 bf16 -> f32 (portable, sm_80+)
__device__ __forceinline__ void mma16816(float* d, const uint32_t* a, uint32_t b0, uint32_t b1) {
    asm("mma.sync.aligned.m16n8k16.row.col.f32.bf16.bf16.f32 "
        "{%0,%1,%2,%3}, {%4,%5,%6,%7}, {%8,%9}, {%0,%1,%2,%3};"
        : "+f"(d[0]), "+f"(d[1]), "+f"(d[2]), "+f"(d[3])
        : "r"(a[0]), "r"(a[1]), "r"(a[2]), "r"(a[3]), "r"(b0), "r"(b1));
}

// ---------------- K1a: per-vocab duration table ----------------
__global__ void k_durtab(const float* __restrict__ embed, const float* __restrict__ dpw,
                         const float* __restrict__ dpb) {
    __shared__ float w[EMB_];
    int t = threadIdx.x;
    if (t < EMB_) w[t] = dpw[t];
    __syncthreads();
    const float* e = embed + t * EMB_;
    double acc = (double)dpb[0];
#pragma unroll 8
    for (int k = 0; k < EMB_; k++) acc += (double)e[k] * (double)w[k];
    float d = (float)acc;
    if (d < 0.f) d = 0.f;
    g_durTab[t] = (int)floorf(d) + 1;
}

// ---------------- K1b: per-batch scan + token scatter ----------------
__global__ void k_expand(const int* __restrict__ x) {
    __shared__ int s[T_];
    int b = blockIdx.x, t = threadIdx.x;
    int tokid = x[b * T_ + t];
    s[t] = g_durTab[tokid];
    __syncthreads();
    for (int off = 1; off < T_; off <<= 1) {
        int v = s[t];
        int a = (t >= off) ? s[t - off] : 0;
        __syncthreads();
        s[t] = v + a;
        __syncthreads();
    }
    for (int p = t; p < LMAX_; p += T_) g_tok[b * LMAX_ + p] = 256;
    __syncthreads();
    int st = t ? s[t - 1] : 0;
    int en = s[t];
    if (en > LMAX_) en = LMAX_;
    for (int p = st; p < en; p++) g_tok[b * LMAX_ + p] = tokid;
}

// ---------------- K2: per-vocab input-projection tables (v-chunked x8, dual acc) ----------------
__global__ void __launch_bounds__(256, 1)
k_proj(const float* __restrict__ embed,
       const float* __restrict__ wih_f, const float* __restrict__ bih_f, const float* __restrict__ bhh_f,
       const float* __restrict__ wih_b, const float* __restrict__ bih_b, const float* __restrict__ bhh_b) {
    extern __shared__ float se[];               // [<=33][128]
    int dir = blockIdx.y;
    int chunk = blockIdx.z;
    int v0 = chunk * 33;
    int cnt = 257 - v0; if (cnt > 33) cnt = 33;
    const float* wih = dir ? wih_b : wih_f;
    const float* bi  = dir ? bih_b : bih_f;
    const float* bh  = dir ? bhh_b : bhh_f;
    int tid = threadIdx.x;
    for (int i = tid; i < cnt * 128; i += 256) {
        int v = v0 + (i >> 7);
        se[i] = (v < 256) ? embed[v * 128 + (i & 127)] : 0.f;
    }
    __syncthreads();

    int rloc = tid >> 1, hf = tid & 1;
    int r = blockIdx.x * 128 + rloc;
    ull wreg[32];
    const ulonglong2* wp = (const ulonglong2*)(wih + r * EMB_ + hf * 64);
#pragma unroll
    for (int i = 0; i < 16; i++) { ulonglong2 u = wp[i]; wreg[2 * i] = u.x; wreg[2 * i + 1] = u.y; }
    float bsum = bi[r] + bh[r];

    for (int vv = 0; vv < cnt; vv++) {
        const float* ev = se + vv * 128 + hf * 64;
        ull acc0 = 0ull, acc1 = 0ull;
#pragma unroll
        for (int i = 0; i < 16; i++) {
            ulonglong2 e2 = *(const ulonglong2*)(ev + i * 4);
            acc0 = fma2(wreg[2 * i], e2.x, acc0);
            acc1 = fma2(wreg[2 * i + 1], e2.y, acc1);
        }
        float part = pairsum(acc0) + pairsum(acc1);
        float other = __shfl_xor_sync(0xFFFFFFFFu, part, 1);
        if (hf == 0)
            g_projE[(dir * 257 + v0 + vv) * 1024 + r] = part + other + bsum;
    }
}

// ---------------- K2b: pack linw into HMMA B-fragments (once) ----------------
__global__ void k_linprep(const float* __restrict__ linw) {
    int ww = blockIdx.x * 8 + (threadIdx.x >> 5);   // 0..319 = kt*10+nt
    int lane = threadIdx.x & 31;
    int nt = ww % 10, kt = ww / 10;
    int gid = lane >> 2, tig = lane & 3;
    int n = nt * 8 + gid;
    int k0 = kt * 16 + tig * 2;
    const float* p = linw + n * 512;
    uint32_t h0, l0, h1, l1;
    packhl(p[k0], p[k0 + 1], h0, l0);
    packhl(p[k0 + 8], p[k0 + 9], h1, l1);
    g_linwF[ww * 32 + lane] = make_uint4(h0, h1, l0, l1);
}

// ---------------- K3: persistent cluster biLSTM, HMMA, 4 interleaved groups ----------------
// 8 clusters x 8 CTAs x 512 thr. cluster = (dir, 16-seq quad), split into 4 groups of 4 seqs.
// Per slot: N=4 MMA (cols 4-7 are dup of 0-3 via lane&15 B reads — latency-bound, waste is free).
// 4-deep interleave hides each slot's exchange/chain latency under 3 others' issue work.
// Exchange: proven bulk-copy protocol, 512B x 8 peers per slot (same bytes/step as R11 G=2).
// smem (bytes):
#define FB_OF  0            // fb [q8][rank8][128] u32 = 32768   (q = g*2+p)
#define STG_OF 32768        // stg[q8][128] u32 = 4096
#define SCR_OF 36864        // scr[g4][kh2][128][9] f32 = 36864
#define MB_OF  73728        // 8 mbarriers [g][p]
#define SMEM_LSTM 73792

__global__ void __cluster_dims__(8, 1, 1) __launch_bounds__(512, 1)
k_lstm(const float* __restrict__ whh_f, const float* __restrict__ whh_b, int L) {
    extern __shared__ __align__(1024) char sm[];
    uint32_t* fb  = (uint32_t*)(sm + FB_OF);
    float*    scr = (float*)(sm + SCR_OF);

    int tid = threadIdx.x;
    int w = tid >> 5, lane = tid & 31;
    int gid = lane >> 2, tig = lane & 3;
    int bx = blockIdx.x;
    int rank = bx & 7;
    int cid = bx >> 3;
    int dir = cid >> 2;
    int quad = cid & 3;
    const float* whh = dir ? whh_b : whh_f;

    uint32_t sm_s = (uint32_t)__cvta_generic_to_shared(sm);
    uint32_t fb_s = sm_s + FB_OF;
    uint32_t st_s = sm_s + STG_OF;
    uint32_t mb_s = sm_s + MB_OF;

    // ---- Whh slice -> A fragments (bf16 hi/lo) in registers, loaded once ----
    int mt = w & 7, kh = w >> 3;
    uint32_t ahi[8][4], alo[8][4];
    {
        int m0 = mt * 16 + gid, m1 = m0 + 8;
        int g0 = (m0 >> 5) * 256 + rank * 32 + (m0 & 31);
        int g1 = (m1 >> 5) * 256 + rank * 32 + (m1 & 31);
        const float* r0 = whh + g0 * 256 + kh * 128;
        const float* r1 = whh + g1 * 256 + kh * 128;
#pragma unroll
        for (int kt = 0; kt < 8; kt++) {
            int c0 = kt * 16 + tig * 2;
            float2 v;
            v = *(const float2*)(r0 + c0);     packhl(v.x, v.y, ahi[kt][0], alo[kt][0]);
            v = *(const float2*)(r1 + c0);     packhl(v.x, v.y, ahi[kt][1], alo[kt][1]);
            v = *(const float2*)(r0 + c0 + 8); packhl(v.x, v.y, ahi[kt][2], alo[kt][2]);
            v = *(const float2*)(r1 + c0 + 8); packhl(v.x, v.y, ahi[kt][3], alo[kt][3]);
        }
    }

    for (int i = tid; i < 8192; i += 512) fb[i] = 0u;    // h=0 in all groups/phases

    if (tid == 0) {
#pragma unroll
        for (int q = 0; q < 8; q++) mbar_init(mb_s + 8 * q, 1);
        asm volatile("fence.mbarrier_init.release.cluster;" ::: "memory");
#pragma unroll
        for (int q = 0; q < 8; q++) mbar_arrive_expect(mb_s + 8 * q, 4096);
    }
    __syncthreads();
    cluster_sync();

    bool s2t = tid < 128;                    // stage-2 threads: b2 = warp (0..3), j2 = lane
    int b2 = tid >> 5, j2 = tid & 31;
    float cst[4] = {0.f, 0.f, 0.f, 0.f};     // cell state per group
    unsigned parr = 0;                       // parity bit per q = g*2+p
    int p = 0;

    for (int s = 0; s < L; s++) {
        int pos = dir ? (L - 1 - s) : s;
#pragma unroll
        for (int g = 0; g < 4; g++) {
            int bg = quad * 16 + g * 4 + b2;
            float p_i = 0.f, p_f = 0.f, p_g = 0.f, p_o = 0.f;
            if (s2t) {                       // early gathers, consumed after HMMA
                int tok = g_tok[bg * LMAX_ + pos];
                const float* pe = g_projE + (dir * 257 + tok) * 1024 + rank * 32 + j2;
                p_i = pe[0]; p_f = pe[256]; p_g = pe[512]; p_o = pe[768];
            }
            int q = g * 2 + p;
            if (s > 0) {
                mbar_wait(mb_s + 8 * q, (parr >> q) & 1);
                parr ^= 1u << q;
                if (tid == 0) mbar_arrive_expect(mb_s + 8 * q, 4096);   // rearm 2 steps ahead
            }

            // ---- HMMA: D[128x4(+dup)] = Whh_slice . h_g  (3 products, 2 acc chains) ----
            {
                const uint32_t* fbg = fb + q * 1024;
                float a0[4] = {0.f, 0.f, 0.f, 0.f};
                float a1[4] = {0.f, 0.f, 0.f, 0.f};
                int ll = (lane & 15) * 2;
#pragma unroll
                for (int kt = 0; kt < 8; kt++) {
                    const uint32_t* base = fbg + (kh * 8 + kt) * 64;
                    uint2 bh = *(const uint2*)(base + ll);
                    uint2 bl = *(const uint2*)(base + 32 + ll);
                    mma16816(a0, ahi[kt], bh.x, bh.y);
                    mma16816(a1, ahi[kt], bl.x, bl.y);
                    mma16816(a1, alo[kt], bh.x, bh.y);
                }
                float* sc = scr + (g * 2 + kh) * 1152;
                int m0 = mt * 16 + gid, n0 = tig * 2;
                sc[m0 * 9 + n0]           = a0[0] + a1[0];
                sc[m0 * 9 + n0 + 1]       = a0[1] + a1[1];
                sc[(m0 + 8) * 9 + n0]     = a0[2] + a1[2];
                sc[(m0 + 8) * 9 + n0 + 1] = a0[3] + a1[3];
            }

            if (s2t) {
                // consumers: wait for all 16 warps' scr writes (per-group barrier id)
                asm volatile("bar.sync %0, 512;" :: "r"(1 + g) : "memory");
                // ---- stage 2: gates + state update + fragment pack ----
                const float* s0 = scr + (g * 2) * 1152;
                const float* s1 = scr + (g * 2 + 1) * 1152;
                float gi = p_i + s0[(      j2) * 9 + b2] + s1[(      j2) * 9 + b2];
                float gf = p_f + s0[( 32 + j2) * 9 + b2] + s1[( 32 + j2) * 9 + b2];
                float gg = p_g + s0[( 64 + j2) * 9 + b2] + s1[( 64 + j2) * 9 + b2];
                float go = p_o + s0[( 96 + j2) * 9 + b2] + s1[( 96 + j2) * 9 + b2];
                float c = sigf(gf) * cst[g] + sigf(gi) * tanhf_(gg);
                cst[g] = c;
                float h = sigf(go) * tanhf_(c);

                g_hout[(((size_t)dir * 64 + bg) * L + pos) * 256 + rank * 32 + j2] = h;

                if (s + 1 < L) {             // pack h -> bf16 hi/lo, compact N=4 frag layout
                    unsigned short hh = bfb(h);
                    unsigned short lh = bfb(h - bff(hh));
                    int ktg_l = j2 >> 4, reg = (j2 >> 3) & 1, tg = (j2 >> 1) & 3, hw = j2 & 1;
                    uint32_t ehi = (uint32_t)(q * 128 + ktg_l * 64 + (b2 * 4 + tg) * 2 + reg);
                    uint32_t elo = ehi + 32;
                    asm volatile("st.shared.u16 [%0], %1;"
                                 :: "r"(st_s + ehi * 4 + hw * 2), "h"(hh) : "memory");
                    asm volatile("st.shared.u16 [%0], %1;"
                                 :: "r"(st_s + elo * 4 + hw * 2), "h"(lh) : "memory");
                    asm volatile("bar.sync 5, 128;" ::: "memory");   // stage-2 warps only
                    if (tid < 8) {           // 8 x 512B fragment copies to peers
                        asm volatile("fence.proxy.async.shared::cta;" ::: "memory");
                        uint32_t qn = (uint32_t)(g * 2 + (p ^ 1));
                        uint32_t dst = fb_s + (qn * 1024 + (uint32_t)rank * 128) * 4;
                        uint32_t mb  = mb_s + qn * 8;
                        uint32_t src = st_s + (uint32_t)(q * 512);
                        uint32_t ra, rm;
                        asm volatile("mapa.shared::cluster.u32 %0, %1, %2;" : "=r"(ra) : "r"(dst), "r"(tid));
                        asm volatile("mapa.shared::cluster.u32 %0, %1, %2;" : "=r"(rm) : "r"(mb), "r"(tid));
                        s2s_bulk(ra, src, 512, rm);
                    }
                }
            } else {
                // producers: post arrival on this group's barrier, run ahead
                asm volatile("bar.arrive %0, 512;" :: "r"(1 + g) : "memory");
            }
        }
        p ^= 1;
    }
    cluster_sync();                          // exit safety
}

// ---------------- K4: final linear on HMMA: (B*L, 512) @ (512, 80) + bias ----------------
#define LIN_SMEM (163840 + 512)
__global__ void __launch_bounds__(256, 1)
k_lin(const float* __restrict__ linb, float* __restrict__ out, int L, int R) {
    extern __shared__ __align__(16) char smc[];
    uint4* sb = (uint4*)smc;                 // [320][32] B-fragments
    float* sbias = (float*)(smc + 163840);
    int tid = threadIdx.x;
    for (int i = tid; i < 10240; i += 256) sb[i] = g_linwF[i];
    if (tid < 80) sbias[tid] = linb[tid];
    __syncthreads();

    int w = tid >> 5, lane = tid & 31, gid = lane >> 2, tig = lane & 3;
    int r0 = blockIdx.x * 128 + w * 16;
    int ra = r0 + gid, rb = r0 + gid + 8;
    bool va = ra < R, vb = rb < R;
    int raz = va ? ra : 0, rbz = vb ? rb : 0;
    int ba = raz / L, pa = raz % L, bb = rbz / L, pb = rbz % L;
    const float* pa0 = g_hout + ((size_t)ba * L + pa) * 256;
    const float* pa1 = g_hout + ((size_t)(64 + ba) * L + pa) * 256;
    const float* pb0 = g_hout + ((size_t)bb * L + pb) * 256;
    const float* pb1 = g_hout + ((size_t)(64 + bb) * L + pb) * 256;

    float acc[10][4];
#pragma unroll
    for (int nt = 0; nt < 10; nt++)
#pragma unroll
        for (int i = 0; i < 4; i++) acc[nt][i] = 0.f;

#pragma unroll 4
    for (int kt = 0; kt < 32; kt++) {
        const float* qa = (kt < 16) ? pa0 : pa1;
        const float* qb = (kt < 16) ? pb0 : pb1;
        int c0 = ((kt * 16) & 255) + tig * 2;
        float2 z = make_float2(0.f, 0.f);
        float2 a00 = va ? *(const float2*)(qa + c0)     : z;
        float2 a10 = vb ? *(const float2*)(qb + c0)     : z;
        float2 a01 = va ? *(const float2*)(qa + c0 + 8) : z;
        float2 a11 = vb ? *(const float2*)(qb + c0 + 8) : z;
        uint32_t ahi[4], alo[4];
        packhl(a00.x, a00.y, ahi[0], alo[0]);
        packhl(a10.x, a10.y, ahi[1], alo[1]);
        packhl(a01.x, a01.y, ahi[2], alo[2]);
        packhl(a11.x, a11.y, ahi[3], alo[3]);
        const uint4* bp = sb + kt * 320 + lane;
#pragma unroll
        for (int nt = 0; nt < 10; nt++) {
            uint4 bf = bp[nt * 32];
            mma16816(acc[nt], ahi, bf.x, bf.y);   // hi*hi
            mma16816(acc[nt], ahi, bf.z, bf.w);   // hi*lo
            mma16816(acc[nt], alo, bf.x, bf.y);   // lo*hi
        }
    }
#pragma unroll
    for (int nt = 0; nt < 10; nt++) {
        int n0 = nt * 8 + tig * 2;
        float b0 = sbias[n0], b1 = sbias[n0 + 1];
        if (va) {
            out[(size_t)ra * MEL_ + n0]     = acc[nt][0] + b0;
            out[(size_t)ra * MEL_ + n0 + 1] = acc[nt][1] + b1;
        }
        if (vb) {
            out[(size_t)rb * MEL_ + n0]     = acc[nt][2] + b0;
            out[(size_t)rb * MEL_ + n0 + 1] = acc[nt][3] + b1;
        }
    }
}

// ---------------- launch ----------------
extern "C" void kernel_launch(void* const* d_in, const int* in_sizes, int n_in,
                              void* d_out, int out_size) {
    const int*   x     = (const int*)  d_in[0];
    const float* embed = (const float*)d_in[1];
    const float* dpw   = (const float*)d_in[2];
    const float* dpb   = (const float*)d_in[3];
    const float* wihf  = (const float*)d_in[4];
    const float* whhf  = (const float*)d_in[5];
    const float* bihf  = (const float*)d_in[6];
    const float* bhhf  = (const float*)d_in[7];
    const float* wihb  = (const float*)d_in[8];
    const float* whhb  = (const float*)d_in[9];
    const float* bihb  = (const float*)d_in[10];
    const float* bhhb  = (const float*)d_in[11];
    const float* linw  = (const float*)d_in[12];
    const float* linb  = (const float*)d_in[13];
    float* out = (float*)d_out;

    int L = out_size / (B_ * MEL_);
    if (L > LMAX_) L = LMAX_;
    int R = B_ * L;

    k_durtab<<<1, 256>>>(embed, dpw, dpb);
    k_expand<<<B_, T_>>>(x);
    k_linprep<<<40, 256>>>(linw);

    int smem_proj = 33 * 128 * 4;              // 16,896 B
    cudaFuncSetAttribute(k_proj, cudaFuncAttributeMaxDynamicSharedMemorySize, smem_proj);
    k_proj<<<dim3(8, 2, 8), 256, smem_proj>>>(embed, wihf, bihf, bhhf, wihb, bihb, bhhb);

    cudaFuncSetAttribute(k_lstm, cudaFuncAttributeMaxDynamicSharedMemorySize, SMEM_LSTM);
    k_lstm<<<64, 512, SMEM_LSTM>>>(whhf, whhb, L);

    cudaFuncSetAttribute(k_lin, cudaFuncAttributeMaxDynamicSharedMemorySize, LIN_SMEM);
    k_lin<<<(R + 127) / 128, 256, LIN_SMEM>>>(linb, out, L, R);
}

// round 17
// speedup vs baseline: 1.9278x; 1.9278x over previous
#include <cuda_runtime.h>
#include <cuda_bf16.h>
#include <cstdint>
#include <cstdio>

#define B_ 64
#define T_ 512
#define EMB_ 128
#define HID_ 256
#define MEL_ 80
#define LMAX_ 2048

typedef unsigned long long ull;

// ---------------- static device scratch ----------------
__device__ int   g_durTab[256];
__device__ int   g_tok[B_ * LMAX_];                 // vocab id per expanded pos, 256 = pad
__device__ float g_projE[2 * 257 * 1024];           // Wih@embed[v] + bih + bhh  (entry 256 = bias only)
__device__ float g_hout[2ull * B_ * LMAX_ * HID_];  // [dir][b][pos][256]
__device__ uint4 g_linwF[320 * 32];                 // linw as B-frags: [kt*10+nt][lane]{hi0,hi1,lo0,lo1}

// ---------------- generic helpers ----------------
__device__ __forceinline__ ull fma2(ull a, ull b, ull c) {
    ull d;
    asm("fma.rn.f32x2 %0, %1, %2, %3;" : "=l"(d) : "l"(a), "l"(b), "l"(c));
    return d;
}
__device__ __forceinline__ float pairsum(ull v) {
    float x, y;
    asm("mov.b64 {%0, %1}, %2;" : "=f"(x), "=f"(y) : "l"(v));
    return x + y;
}
__device__ __forceinline__ float sigf(float x)  { return __fdividef(1.f, 1.f + __expf(-x)); }
__device__ __forceinline__ float tanhf_(float x){ return 1.f - __fdividef(2.f, 1.f + __expf(2.f * x)); }

__device__ __forceinline__ void cluster_sync() {
    asm volatile("barrier.cluster.arrive.aligned;" ::: "memory");
    asm volatile("barrier.cluster.wait.aligned;" ::: "memory");
}
__device__ __forceinline__ void mbar_init(uint32_t a, uint32_t cnt) {
    asm volatile("mbarrier.init.shared.b64 [%0], %1;" :: "r"(a), "r"(cnt) : "memory");
}
__device__ __forceinline__ void mbar_arrive_expect(uint32_t a, uint32_t tx) {
    asm volatile("mbarrier.arrive.expect_tx.shared.b64 _, [%0], %1;" :: "r"(a), "r"(tx) : "memory");
}
__device__ __forceinline__ void mbar_wait(uint32_t a, uint32_t par) {
    asm volatile(
        "{\n\t"
        ".reg .pred P;\n\t"
        "W%=:\n\t"
        "mbarrier.try_wait.parity.acquire.cluster.shared::cta.b64 P, [%0], %1, 0x989680;\n\t"
        "@P bra D%=;\n\t"
        "bra W%=;\n\t"
        "D%=:\n\t"
        "}"
        :: "r"(a), "r"(par) : "memory");
}
__device__ __forceinline__ void s2s_bulk(uint32_t dst, uint32_t src, uint32_t bytes, uint32_t rmbar) {
    asm volatile("cp.async.bulk.shared::cluster.shared::cta.mbarrier::complete_tx::bytes [%0], [%1], %2, [%3];"
                 :: "r"(dst), "r"(src), "r"(bytes), "r"(rmbar) : "memory");
}

__device__ __forceinline__ unsigned short bfb(float x) {
    __nv_bfloat16 h = __float2bfloat16(x);
    return reinterpret_cast<unsigned short&>(h);
}
__device__ __forceinline__ float bff(unsigned short u) {
    __nv_bfloat16 h = reinterpret_cast<__nv_bfloat16&>(u);
    return __bfloat162float(h);
}
__device__ __forceinline__ void packhl(float x, float y, uint32_t& hi, uint32_t& lo) {
    unsigned short h0 = bfb(x), h1 = bfb(y);
    float r0 = x - bff(h0), r1 = y - bff(h1);
    hi = (uint32_t)h0 | ((uint32_t)h1 << 16);
    lo = (uint32_t)bfb(r0) | ((uint32_t)bfb(r1) << 16);
}

// HMMA m16n8k16 bf16 -> f32 (portable, sm_80+)
__device__ __forceinline__ void mma16816(float* d, const uint32_t* a, uint32_t b0, uint32_t b1) {
    asm("mma.sync.aligned.m16n8k16.row.col.f32.bf16.bf16.f32 "
        "{%0,%1,%2,%3}, {%4,%5,%6,%7}, {%8,%9}, {%0,%1,%2,%3};"
        : "+f"(d[0]), "+f"(d[1]), "+f"(d[2]), "+f"(d[3])
        : "r"(a[0]), "r"(a[1]), "r"(a[2]), "r"(a[3]), "r"(b0), "r"(b1));
}

// ---------------- K1a: per-vocab duration table ----------------
__global__ void k_durtab(const float* __restrict__ embed, const float* __restrict__ dpw,
                         const float* __restrict__ dpb) {
    __shared__ float w[EMB_];
    int t = threadIdx.x;
    if (t < EMB_) w[t] = dpw[t];
    __syncthreads();
    const float* e = embed + t * EMB_;
    double acc = (double)dpb[0];
#pragma unroll 8
    for (int k = 0; k < EMB_; k++) acc += (double)e[k] * (double)w[k];
    float d = (float)acc;
    if (d < 0.f) d = 0.f;
    g_durTab[t] = (int)floorf(d) + 1;
}

// ---------------- K1b: per-batch scan + token scatter ----------------
__global__ void k_expand(const int* __restrict__ x) {
    __shared__ int s[T_];
    int b = blockIdx.x, t = threadIdx.x;
    int tokid = x[b * T_ + t];
    s[t] = g_durTab[tokid];
    __syncthreads();
    for (int off = 1; off < T_; off <<= 1) {
        int v = s[t];
        int a = (t >= off) ? s[t - off] : 0;
        __syncthreads();
        s[t] = v + a;
        __syncthreads();
    }
    for (int p = t; p < LMAX_; p += T_) g_tok[b * LMAX_ + p] = 256;
    __syncthreads();
    int st = t ? s[t - 1] : 0;
    int en = s[t];
    if (en > LMAX_) en = LMAX_;
    for (int p = st; p < en; p++) g_tok[b * LMAX_ + p] = tokid;
}

// ---------------- K2: per-vocab input-projection tables (v-chunked x8, dual acc) ----------------
__global__ void __launch_bounds__(256, 1)
k_proj(const float* __restrict__ embed,
       const float* __restrict__ wih_f, const float* __restrict__ bih_f, const float* __restrict__ bhh_f,
       const float* __restrict__ wih_b, const float* __restrict__ bih_b, const float* __restrict__ bhh_b) {
    extern __shared__ float se[];               // [<=33][128]
    int dir = blockIdx.y;
    int chunk = blockIdx.z;
    int v0 = chunk * 33;
    int cnt = 257 - v0; if (cnt > 33) cnt = 33;
    const float* wih = dir ? wih_b : wih_f;
    const float* bi  = dir ? bih_b : bih_f;
    const float* bh  = dir ? bhh_b : bhh_f;
    int tid = threadIdx.x;
    for (int i = tid; i < cnt * 128; i += 256) {
        int v = v0 + (i >> 7);
        se[i] = (v < 256) ? embed[v * 128 + (i & 127)] : 0.f;
    }
    __syncthreads();

    int rloc = tid >> 1, hf = tid & 1;
    int r = blockIdx.x * 128 + rloc;
    ull wreg[32];
    const ulonglong2* wp = (const ulonglong2*)(wih + r * EMB_ + hf * 64);
#pragma unroll
    for (int i = 0; i < 16; i++) { ulonglong2 u = wp[i]; wreg[2 * i] = u.x; wreg[2 * i + 1] = u.y; }
    float bsum = bi[r] + bh[r];

    for (int vv = 0; vv < cnt; vv++) {
        const float* ev = se + vv * 128 + hf * 64;
        ull acc0 = 0ull, acc1 = 0ull;
#pragma unroll
        for (int i = 0; i < 16; i++) {
            ulonglong2 e2 = *(const ulonglong2*)(ev + i * 4);
            acc0 = fma2(wreg[2 * i], e2.x, acc0);
            acc1 = fma2(wreg[2 * i + 1], e2.y, acc1);
        }
        float part = pairsum(acc0) + pairsum(acc1);
        float other = __shfl_xor_sync(0xFFFFFFFFu, part, 1);
        if (hf == 0)
            g_projE[(dir * 257 + v0 + vv) * 1024 + r] = part + other + bsum;
    }
}

// ---------------- K2b: pack linw into HMMA B-fragments (once) ----------------
__global__ void k_linprep(const float* __restrict__ linw) {
    int ww = blockIdx.x * 8 + (threadIdx.x >> 5);   // 0..319 = kt*10+nt
    int lane = threadIdx.x & 31;
    int nt = ww % 10, kt = ww / 10;
    int gid = lane >> 2, tig = lane & 3;
    int n = nt * 8 + gid;
    int k0 = kt * 16 + tig * 2;
    const float* p = linw + n * 512;
    uint32_t h0, l0, h1, l1;
    packhl(p[k0], p[k0 + 1], h0, l0);
    packhl(p[k0 + 8], p[k0 + 9], h1, l1);
    g_linwF[ww * 32 + lane] = make_uint4(h0, h1, l0, l1);
}

// ---------------- K3: persistent cluster biLSTM, HMMA, 2 interleaved groups (R11 base) ----
// 8 clusters x 8 CTAs x 512 thr. Producer warps (8-15) bar.arrive on per-group ids and run
// ahead; rearm by a producer thread (off the consumer chain). Bulk-copy exchange (proven).
// smem (bytes):
#define FB_OF  0            // fb [g2][p2][ktg16][hl2][lane32][reg2] u32 = 32768
#define STG_OF 32768        // stg[g2][p2][256] u32 = 4096
#define SCR_OF 36864        // scr[g2][kh2][128][9] f32 = 36864
#define MB_OF  73728        // 4 mbarriers [g][p]
#define SMEM_LSTM 73792

__global__ void __cluster_dims__(8, 1, 1) __launch_bounds__(512, 1)
k_lstm(const float* __restrict__ whh_f, const float* __restrict__ whh_b, int L) {
    extern __shared__ __align__(1024) char sm[];
    uint32_t* fb  = (uint32_t*)(sm + FB_OF);
    float*    scr = (float*)(sm + SCR_OF);

    int tid = threadIdx.x;
    int w = tid >> 5, lane = tid & 31;
    int gid = lane >> 2, tig = lane & 3;
    int bx = blockIdx.x;
    int rank = bx & 7;
    int cid = bx >> 3;
    int dir = cid >> 2;
    int quad = cid & 3;
    const float* whh = dir ? whh_b : whh_f;

    uint32_t sm_s = (uint32_t)__cvta_generic_to_shared(sm);
    uint32_t fb_s = sm_s + FB_OF;
    uint32_t st_s = sm_s + STG_OF;
    uint32_t mb_s = sm_s + MB_OF;

    // ---- Whh slice -> A fragments (bf16 hi/lo) in registers, loaded once ----
    int mt = w & 7, kh = w >> 3;
    uint32_t ahi[8][4], alo[8][4];
    {
        int m0 = mt * 16 + gid, m1 = m0 + 8;
        int g0 = (m0 >> 5) * 256 + rank * 32 + (m0 & 31);
        int g1 = (m1 >> 5) * 256 + rank * 32 + (m1 & 31);
        const float* r0 = whh + g0 * 256 + kh * 128;
        const float* r1 = whh + g1 * 256 + kh * 128;
#pragma unroll
        for (int kt = 0; kt < 8; kt++) {
            int c0 = kt * 16 + tig * 2;
            float2 v;
            v = *(const float2*)(r0 + c0);     packhl(v.x, v.y, ahi[kt][0], alo[kt][0]);
            v = *(const float2*)(r1 + c0);     packhl(v.x, v.y, ahi[kt][1], alo[kt][1]);
            v = *(const float2*)(r0 + c0 + 8); packhl(v.x, v.y, ahi[kt][2], alo[kt][2]);
            v = *(const float2*)(r1 + c0 + 8); packhl(v.x, v.y, ahi[kt][3], alo[kt][3]);
        }
    }

    for (int i = tid; i < 8192; i += 512) fb[i] = 0u;    // h=0 in both groups/phases

    if (tid == 0) {
#pragma unroll
        for (int q = 0; q < 4; q++) mbar_init(mb_s + 8 * q, 1);
        asm volatile("fence.mbarrier_init.release.cluster;" ::: "memory");
#pragma unroll
        for (int q = 0; q < 4; q++) mbar_arrive_expect(mb_s + 8 * q, 8192);
    }
    __syncthreads();
    cluster_sync();

    bool s2t = tid < 256;                    // stage-2 threads: b2 = warp, j2 = lane
    int b2 = tid >> 5, j2 = tid & 31;
    float cst[2] = {0.f, 0.f};
    unsigned parr = 0;                       // parity bit per q = g*2+p
    int p = 0;

    for (int s = 0; s < L; s++) {
        int pos = dir ? (L - 1 - s) : s;
#pragma unroll
        for (int g = 0; g < 2; g++) {
            int bg = quad * 16 + g * 8 + b2;
            float p_i = 0.f, p_f = 0.f, p_g = 0.f, p_o = 0.f;
            if (s2t) {                       // early gathers, consumed after HMMA
                int tok = g_tok[bg * LMAX_ + pos];
                const float* pe = g_projE + (dir * 257 + tok) * 1024 + rank * 32 + j2;
                p_i = pe[0]; p_f = pe[256]; p_g = pe[512]; p_o = pe[768];
            }
            int q = g * 2 + p;
            if (s > 0) {
                mbar_wait(mb_s + 8 * q, (parr >> q) & 1);
                parr ^= 1u << q;
                if (tid == 504) mbar_arrive_expect(mb_s + 8 * q, 8192);  // rearm by producer
            }

            // ---- HMMA: D[128x8] = Whh_slice . h_g  (3 products, 2 acc chains) ----
            {
                const uint32_t* fbg = fb + q * 2048;
                float a0[4] = {0.f, 0.f, 0.f, 0.f};
                float a1[4] = {0.f, 0.f, 0.f, 0.f};
#pragma unroll
                for (int kt = 0; kt < 8; kt++) {
                    const uint32_t* base = fbg + (kh * 8 + kt) * 128;
                    uint2 bh = *(const uint2*)(base + lane * 2);
                    uint2 bl = *(const uint2*)(base + 64 + lane * 2);
                    mma16816(a0, ahi[kt], bh.x, bh.y);
                    mma16816(a1, ahi[kt], bl.x, bl.y);
                    mma16816(a1, alo[kt], bh.x, bh.y);
                }
                float* sc = scr + (g * 2 + kh) * 1152;
                int m0 = mt * 16 + gid, n0 = tig * 2;
                sc[m0 * 9 + n0]           = a0[0] + a1[0];
                sc[m0 * 9 + n0 + 1]       = a0[1] + a1[1];
                sc[(m0 + 8) * 9 + n0]     = a0[2] + a1[2];
                sc[(m0 + 8) * 9 + n0 + 1] = a0[3] + a1[3];
            }

            if (s2t) {
                // consumers: wait for all 16 warps' scr writes (per-group barrier id)
                asm volatile("bar.sync %0, 512;" :: "r"(1 + g) : "memory");
                // ---- stage 2: gates + state update + fragment pack ----
                const float* s0 = scr + (g * 2) * 1152;
                const float* s1 = scr + (g * 2 + 1) * 1152;
                float gi = p_i + s0[(      j2) * 9 + b2] + s1[(      j2) * 9 + b2];
                float gf = p_f + s0[( 32 + j2) * 9 + b2] + s1[( 32 + j2) * 9 + b2];
                float gg = p_g + s0[( 64 + j2) * 9 + b2] + s1[( 64 + j2) * 9 + b2];
                float go = p_o + s0[( 96 + j2) * 9 + b2] + s1[( 96 + j2) * 9 + b2];
                float c = sigf(gf) * cst[g] + sigf(gi) * tanhf_(gg);
                cst[g] = c;
                float h = sigf(go) * tanhf_(c);

                g_hout[(((size_t)dir * 64 + bg) * L + pos) * 256 + rank * 32 + j2] = h;

                if (s + 1 < L) {             // pack h -> bf16 hi/lo directly in fragment layout
                    unsigned short hh = bfb(h);
                    unsigned short lh = bfb(h - bff(hh));
                    int ktg_l = j2 >> 4, reg = (j2 >> 3) & 1, tg = (j2 >> 1) & 3, hw = j2 & 1;
                    uint32_t base16 = (uint32_t)(q * 256);
                    uint32_t ehi = ((ktg_l * 2 + 0) * 32 + b2 * 4 + tg) * 2 + reg;
                    uint32_t elo = ((ktg_l * 2 + 1) * 32 + b2 * 4 + tg) * 2 + reg;
                    asm volatile("st.shared.u16 [%0], %1;"
                                 :: "r"(st_s + (base16 + ehi) * 4 + hw * 2), "h"(hh) : "memory");
                    asm volatile("st.shared.u16 [%0], %1;"
                                 :: "r"(st_s + (base16 + elo) * 4 + hw * 2), "h"(lh) : "memory");
                    asm volatile("bar.sync 3, 256;" ::: "memory");   // stage-2 warps only
                    if (tid < 8) {           // 8 x 1KB fragment copies to peers
                        asm volatile("fence.proxy.async.shared::cta;" ::: "memory");
                        uint32_t dst = fb_s + (uint32_t)(((g * 2 + (p ^ 1)) * 2048 + rank * 256) * 4);
                        uint32_t mb  = mb_s + (uint32_t)((g * 2 + (p ^ 1)) * 8);
                        uint32_t src = st_s + (uint32_t)(q * 1024);
                        uint32_t ra, rm;
                        asm volatile("mapa.shared::cluster.u32 %0, %1, %2;" : "=r"(ra) : "r"(dst), "r"(tid));
                        asm volatile("mapa.shared::cluster.u32 %0, %1, %2;" : "=r"(rm) : "r"(mb), "r"(tid));
                        s2s_bulk(ra, src, 1024, rm);
                    }
                }
            } else {
                // producers: post arrival on this group's barrier, run ahead
                asm volatile("bar.arrive %0, 512;" :: "r"(1 + g) : "memory");
            }
        }
        p ^= 1;
    }
    cluster_sync();                          // exit safety
}

// ---------------- K4: final linear on HMMA: (B*L, 512) @ (512, 80) + bias ----------------
#define LIN_SMEM (163840 + 512)
__global__ void __launch_bounds__(256, 1)
k_lin(const float* __restrict__ linb, float* __restrict__ out, int L, int R) {
    extern __shared__ __align__(16) char smc[];
    uint4* sb = (uint4*)smc;                 // [320][32] B-fragments
    float* sbias = (float*)(smc + 163840);
    int tid = threadIdx.x;
    for (int i = tid; i < 10240; i += 256) sb[i] = g_linwF[i];
    if (tid < 80) sbias[tid] = linb[tid];
    __syncthreads();

    int w = tid >> 5, lane = tid & 31, gid = lane >> 2, tig = lane & 3;
    int r0 = blockIdx.x * 128 + w * 16;
    int ra = r0 + gid, rb = r0 + gid + 8;
    bool va = ra < R, vb = rb < R;
    int raz = va ? ra : 0, rbz = vb ? rb : 0;
    int ba = raz / L, pa = raz % L, bb = rbz / L, pb = rbz % L;
    const float* pa0 = g_hout + ((size_t)ba * L + pa) * 256;
    const float* pa1 = g_hout + ((size_t)(64 + ba) * L + pa) * 256;
    const float* pb0 = g_hout + ((size_t)bb * L + pb) * 256;
    const float* pb1 = g_hout + ((size_t)(64 + bb) * L + pb) * 256;

    float acc[10][4];
#pragma unroll
    for (int nt = 0; nt < 10; nt++)
#pragma unroll
        for (int i = 0; i < 4; i++) acc[nt][i] = 0.f;

#pragma unroll 4
    for (int kt = 0; kt < 32; kt++) {
        const float* qa = (kt < 16) ? pa0 : pa1;
        const float* qb = (kt < 16) ? pb0 : pb1;
        int c0 = ((kt * 16) & 255) + tig * 2;
        float2 z = make_float2(0.f, 0.f);
        float2 a00 = va ? *(const float2*)(qa + c0)     : z;
        float2 a10 = vb ? *(const float2*)(qb + c0)     : z;
        float2 a01 = va ? *(const float2*)(qa + c0 + 8) : z;
        float2 a11 = vb ? *(const float2*)(qb + c0 + 8) : z;
        uint32_t ahi[4], alo[4];
        packhl(a00.x, a00.y, ahi[0], alo[0]);
        packhl(a10.x, a10.y, ahi[1], alo[1]);
        packhl(a01.x, a01.y, ahi[2], alo[2]);
        packhl(a11.x, a11.y, ahi[3], alo[3]);
        const uint4* bp = sb + kt * 320 + lane;
#pragma unroll
        for (int nt = 0; nt < 10; nt++) {
            uint4 bf = bp[nt * 32];
            mma16816(acc[nt], ahi, bf.x, bf.y);   // hi*hi
            mma16816(acc[nt], ahi, bf.z, bf.w);   // hi*lo
            mma16816(acc[nt], alo, bf.x, bf.y);   // lo*hi
        }
    }
#pragma unroll
    for (int nt = 0; nt < 10; nt++) {
        int n0 = nt * 8 + tig * 2;
        float b0 = sbias[n0], b1 = sbias[n0 + 1];
        if (va) {
            out[(size_t)ra * MEL_ + n0]     = acc[nt][0] + b0;
            out[(size_t)ra * MEL_ + n0 + 1] = acc[nt][1] + b1;
        }
        if (vb) {
            out[(size_t)rb * MEL_ + n0]     = acc[nt][2] + b0;
            out[(size_t)rb * MEL_ + n0 + 1] = acc[nt][3] + b1;
        }
    }
}

// ---------------- launch ----------------
extern "C" void kernel_launch(void* const* d_in, const int* in_sizes, int n_in,
                              void* d_out, int out_size) {
    const int*   x     = (const int*)  d_in[0];
    const float* embed = (const float*)d_in[1];
    const float* dpw   = (const float*)d_in[2];
    const float* dpb   = (const float*)d_in[3];
    const float* wihf  = (const float*)d_in[4];
    const float* whhf  = (const float*)d_in[5];
    const float* bihf  = (const float*)d_in[6];
    const float* bhhf  = (const float*)d_in[7];
    const float* wihb  = (const float*)d_in[8];
    const float* whhb  = (const float*)d_in[9];
    const float* bihb  = (const float*)d_in[10];
    const float* bhhb  = (const float*)d_in[11];
    const float* linw  = (const float*)d_in[12];
    const float* linb  = (const float*)d_in[13];
    float* out = (float*)d_out;

    int L = out_size / (B_ * MEL_);
    if (L > LMAX_) L = LMAX_;
    int R = B_ * L;

    k_durtab<<<1, 256>>>(embed, dpw, dpb);
    k_expand<<<B_, T_>>>(x);
    k_linprep<<<40, 256>>>(linw);

    int smem_proj = 33 * 128 * 4;              // 16,896 B
    cudaFuncSetAttribute(k_proj, cudaFuncAttributeMaxDynamicSharedMemorySize, smem_proj);
    k_proj<<<dim3(8, 2, 8), 256, smem_proj>>>(embed, wihf, bihf, bhhf, wihb, bihb, bhhb);

    cudaFuncSetAttribute(k_lstm, cudaFuncAttributeMaxDynamicSharedMemorySize, SMEM_LSTM);
    k_lstm<<<64, 512, SMEM_LSTM>>>(whhf, whhb, L);

    cudaFuncSetAttribute(k_lin, cudaFuncAttributeMaxDynamicSharedMemorySize, LIN_SMEM);
    k_lin<<<(R + 127) / 128, 256, LIN_SMEM>>>(linb, out, L, R);
}